// round 15
// baseline (speedup 1.0000x reference)
#include <cuda_runtime.h>
#include <cuda_fp16.h>
#include <cstdint>
#include <math.h>

#define BATCH 16
#define SEQ   2048
#define DMODEL 1024
#define HDIM  64
#define NQKV  192

// scratch: q (pre-scaled) | k | v as fp16, [B*S][192]
__device__ __half g_qkv[(size_t)BATCH * SEQ * NQKV];
// fused W (q|k|v) pre-converted to fp16: [1024][192]
__device__ __half g_wh[(size_t)DMODEL * NQKV];

__device__ __forceinline__ float ex2(float x) {
    float r;
    asm("ex2.approx.ftz.f32 %0, %1;" : "=f"(r) : "f"(x));
    return r;
}
__device__ __forceinline__ void cp16(uint32_t dst, const void* src) {
    asm volatile("cp.async.cg.shared.global [%0], [%1], 16;" :: "r"(dst), "l"(src));
}
__device__ __forceinline__ uint32_t packh2(float a, float b) {
    __half2 h = __floats2half2_rn(a, b);
    return *reinterpret_cast<uint32_t*>(&h);
}
__device__ __forceinline__ void mma16(float* d, const uint32_t* a, uint32_t b0, uint32_t b1) {
    asm volatile(
        "mma.sync.aligned.m16n8k16.row.col.f32.f16.f16.f32 "
        "{%0,%1,%2,%3}, {%4,%5,%6,%7}, {%8,%9}, {%0,%1,%2,%3};\n"
        : "+f"(d[0]), "+f"(d[1]), "+f"(d[2]), "+f"(d[3])
        : "r"(a[0]), "r"(a[1]), "r"(a[2]), "r"(a[3]), "r"(b0), "r"(b1));
}
__device__ __forceinline__ void ldsm4(uint32_t& r0, uint32_t& r1, uint32_t& r2, uint32_t& r3, uint32_t a) {
    asm volatile("ldmatrix.sync.aligned.m8n8.x4.shared.b16 {%0,%1,%2,%3}, [%4];"
                 : "=r"(r0), "=r"(r1), "=r"(r2), "=r"(r3) : "r"(a));
}
__device__ __forceinline__ void ldsm4t(uint32_t& r0, uint32_t& r1, uint32_t& r2, uint32_t& r3, uint32_t a) {
    asm volatile("ldmatrix.sync.aligned.m8n8.x4.trans.shared.b16 {%0,%1,%2,%3}, [%4];"
                 : "=r"(r0), "=r"(r1), "=r"(r2), "=r"(r3) : "r"(a));
}

#define QSCALE (0.125f * 1.44269504088896340736f)   // 1/sqrt(64) * log2(e)

// ---------------------------------------------------------------------------
// Kernel 0: convert fused W to fp16 once. 1024*96 half2 elements.
// ---------------------------------------------------------------------------
__global__ __launch_bounds__(256) void wconv_kernel(
    const float* __restrict__ Wq, const float* __restrict__ Wk, const float* __restrict__ Wv)
{
    int id = blockIdx.x * 256 + threadIdx.x;     // 0 .. 98303
    int k  = id / 96;
    int n  = (id % 96) * 2;
    const float* W = (n < 64) ? Wq : ((n < 128) ? Wk : Wv);
    float2 v = *(const float2*)&W[(size_t)k * HDIM + (n & 63)];
    *(uint32_t*)&g_wh[(size_t)k * NQKV + n] = packh2(v.x, v.y);
}

// ---------------------------------------------------------------------------
// Kernel 1: fused QKV projection, fp16 mma (m16n8k16), BK=32.
// Block 128x192, 512 threads (16 warps: 4m x 4n, warp 32x48, mi=2 ni=6).
// B (fp16 weights) via 4-stage cp.async ring; A (x fp32) via depth-2
// register prefetch -> cvt -> double-buffered smem. 1 barrier / 24-HMMA iter.
// ---------------------------------------------------------------------------
#define SA_STR 40                    // halves per A row (80B: 8-row bank cover)
#define SB_STR 200                   // halves per B row (400B, proven layout)
#define A_BUF  (128 * SA_STR * 2)    // 10240 B
#define B_STG  (32 * SB_STR * 2)     // 12800 B
#define QB_OFF (2 * A_BUF)           // 20480
#define QBIAS_OFF (QB_OFF + 4 * B_STG)   // 71680
#define QKV_SMEM (QBIAS_OFF + NQKV * 4)  // 72448

__global__ __launch_bounds__(512, 1) void qkv_kernel(const float* __restrict__ x)
{
    extern __shared__ char qsm[];
    const uint32_t sbase = (uint32_t)__cvta_generic_to_shared(qsm);
    float* sbias = (float*)(qsm + QBIAS_OFF);

    const int tid  = threadIdx.x;
    const int w    = tid >> 5;
    const int lane = tid & 31;
    const int g    = lane >> 2;
    const int c    = lane & 3;
    const int wm   = w >> 2;      // 0..3 (32-row group)
    const int wn   = w & 3;       // 0..3 (48-col group)
    const int m0   = blockIdx.x * 128;

    // ---- A per-thread slots: 128x32 fp32 = 1024 float4, 2/thread ----
    int a_row[2], a_c4[2];
#pragma unroll
    for (int i = 0; i < 2; i++) {
        int id = tid + i * 512;
        a_row[i] = id >> 3;
        a_c4[i]  = (id & 3 | ((id & 4))) ;   // placeholder, fixed below
    }
#pragma unroll
    for (int i = 0; i < 2; i++) {
        int id = tid + i * 512;
        a_row[i] = id >> 3;            // 8 float4 per row
        a_c4[i]  = (id & 7) * 4;       // fp32 col
    }

    // ---- B per-thread cp.async slots: 768 chunks of 16B, 1.5/thread ----
    const int b_chunk0 = tid;
    const int b_chunk1 = tid + 512;
    const bool b2ok = (tid < 256);

    // ---- prologue: bias, B stages 0..2, A regs for kc=0,1 ----
    if (tid < NQKV) {
        // bias loaded from original fp32 pointers passed via const memory? No —
        // bias comes through kernel_launch as separate pointers; loaded in launcher
    }
    // (bias is loaded by a dedicated arg-free trick: see below — we stash it in g_wh? no)
    // bias handled via separate pointer args:
    // -- replaced below --
    ;
    // NOTE: actual bias loading happens in the launcher-provided pointers version.

    // This kernel variant receives bias through x-adjacent launch params — see launch.
    // (placeholder removed in final code path)

    // ---- the real body continues in qkv_main below ----
    // (unreachable)
}

// Clean implementation with bias pointers:
__global__ __launch_bounds__(512, 1) void qkv_main(
    const float* __restrict__ x,
    const float* __restrict__ bq, const float* __restrict__ bk, const float* __restrict__ bv)
{
    extern __shared__ char qsm[];
    const uint32_t sbase = (uint32_t)__cvta_generic_to_shared(qsm);
    float* sbias = (float*)(qsm + QBIAS_OFF);

    const int tid  = threadIdx.x;
    const int w    = tid >> 5;
    const int lane = tid & 31;
    const int g    = lane >> 2;
    const int c    = lane & 3;
    const int wm   = w >> 2;
    const int wn   = w & 3;
    const int m0   = blockIdx.x * 128;

    if (tid < NQKV)
        sbias[tid] = (tid < 64) ? bq[tid] : ((tid < 128) ? bk[tid - 64] : bv[tid - 128]);

    // ---- A slots ----
    int a_row[2], a_c4[2];
#pragma unroll
    for (int i = 0; i < 2; i++) {
        int id = tid + i * 512;
        a_row[i] = id >> 3;
        a_c4[i]  = (id & 7) * 4;
    }

    // ---- B cp.async slot geometry: chunk -> (k-row, 16B col) ----
    // chunk id in [0,768): row = id/24 (0..31), col16 = id%24
    auto issue_B = [&](int stage, int kb) {
        uint32_t dst = sbase + QB_OFF + stage * B_STG;
        {
            int id = tid;
            int row = id / 24, col = id % 24;
            cp16(dst + row * (SB_STR * 2) + col * 16,
                 g_wh + (size_t)(kb + row) * NQKV + col * 8);
        }
        if (tid < 256) {
            int id = tid + 512;
            int row = id / 24, col = id % 24;
            cp16(dst + row * (SB_STR * 2) + col * 16,
                 g_wh + (size_t)(kb + row) * NQKV + col * 8);
        }
    };

    float acc[2][6][4];
#pragma unroll
    for (int mi = 0; mi < 2; mi++)
#pragma unroll
        for (int ni = 0; ni < 6; ni++)
#pragma unroll
            for (int r = 0; r < 4; r++) acc[mi][ni][r] = 0.f;

    // ---- prologue ----
    issue_B(0, 0);
    asm volatile("cp.async.commit_group;" ::: "memory");
    issue_B(1, 32);
    asm volatile("cp.async.commit_group;" ::: "memory");
    issue_B(2, 64);
    asm volatile("cp.async.commit_group;" ::: "memory");

    float4 pa[2][2];   // [slot][per-thread chunk]
#pragma unroll
    for (int s = 0; s < 2; s++)
#pragma unroll
        for (int i = 0; i < 2; i++)
            pa[s][i] = *(const float4*)&x[(size_t)(m0 + a_row[i]) * DMODEL + s * 32 + a_c4[i]];

    const int NITER = DMODEL / 32;   // 32

    for (int kc = 0; kc < NITER; kc++) {
        const int ab = kc & 1;
        // ---- commit A slot ab (fp32 -> fp16 smem) ----
        {
            uint32_t abase = sbase + ab * A_BUF;
#pragma unroll
            for (int i = 0; i < 2; i++) {
                float4 v = pa[ab][i];
                uint2 t = make_uint2(packh2(v.x, v.y), packh2(v.z, v.w));
                asm volatile("st.shared.v2.b32 [%0], {%1, %2};"
                             :: "r"(abase + (a_row[i] * SA_STR + a_c4[i]) * 2),
                                "r"(t.x), "r"(t.y));
            }
        }
        // ---- refill A slot ab with chunk kc+2 ----
        if (kc + 2 < NITER) {
            int kb = (kc + 2) * 32;
#pragma unroll
            for (int i = 0; i < 2; i++)
                pa[ab][i] = *(const float4*)&x[(size_t)(m0 + a_row[i]) * DMODEL + kb + a_c4[i]];
        }

        // ---- B stage kc ready? (stages kc+1, kc+2 still in flight) ----
        asm volatile("cp.async.wait_group 2;" ::: "memory");
        __syncthreads();

        // ---- issue B stage kc+3 (its previous readers finished pre-barrier) ----
        if (kc + 3 < NITER) issue_B((kc + 3) & 3, (kc + 3) * 32);
        asm volatile("cp.async.commit_group;" ::: "memory");

        // ---- compute: BK=32 = two k16 halves, 24 HMMA/warp ----
        const uint32_t abase = sbase + ab * A_BUF;
        const uint32_t bbase = sbase + QB_OFF + (kc & 3) * B_STG;
#pragma unroll
        for (int ks = 0; ks < 2; ks++) {
            uint32_t a[2][4];
#pragma unroll
            for (int mi = 0; mi < 2; mi++) {
                int r0 = 32 * wm + 16 * mi;
                uint32_t ad = abase + (uint32_t)(((r0 + (lane & 15)) * SA_STR + ks * 16) * 2
                                                 + ((lane >> 4) & 1) * 16);
                ldsm4(a[mi][0], a[mi][1], a[mi][2], a[mi][3], ad);
            }
#pragma unroll
            for (int np = 0; np < 6; np += 2) {
                uint32_t b0, b1, b2, b3;
                uint32_t bd = bbase + (uint32_t)((((lane & 15) + ks * 16) * SB_STR) * 2
                                                 + (48 * wn + 8 * (np + (lane >> 4))) * 2);
                ldsm4t(b0, b1, b2, b3, bd);
                mma16(acc[0][np],     a[0], b0, b1);
                mma16(acc[1][np],     a[1], b0, b1);
                mma16(acc[0][np + 1], a[0], b2, b3);
                mma16(acc[1][np + 1], a[1], b2, b3);
            }
        }
    }

    // ---- epilogue: +bias, q*=QSCALE, fp16 store ----
#pragma unroll
    for (int mi = 0; mi < 2; mi++) {
        int r = m0 + 32 * wm + 16 * mi + g;
#pragma unroll
        for (int ni = 0; ni < 6; ni++) {
            int col = 48 * wn + 8 * ni + 2 * c;
            float b0f = sbias[col], b1f = sbias[col + 1];
            float sc = (col < 64) ? QSCALE : 1.0f;
            *(uint32_t*)&g_qkv[(size_t)r * NQKV + col] =
                packh2((acc[mi][ni][0] + b0f) * sc, (acc[mi][ni][1] + b1f) * sc);
            *(uint32_t*)&g_qkv[(size_t)(r + 8) * NQKV + col] =
                packh2((acc[mi][ni][2] + b0f) * sc, (acc[mi][ni][3] + b1f) * sc);
        }
    }
}

// ---------------------------------------------------------------------------
// Kernel 2: causal flash attention (unchanged from R13; 45.6us proven).
// ---------------------------------------------------------------------------
#define SKV_ROW   144
#define SK_BYTES  (64 * SKV_ROW)
#define STAGE_B   (2 * SK_BYTES)
#define ATT_SMEM  (3 * STAGE_B)           // 55296

__device__ __forceinline__ void issue_tile(uint32_t sb, const __half* srcbase, int tid) {
#pragma unroll
    for (int i = 0; i < 8; i++) {
        int id  = tid + i * 128;
        int row = id >> 4;
        int ch  = id & 15;
        const __half* src = srcbase + (size_t)row * NQKV;
        if (ch < 8)
            cp16(sb + row * SKV_ROW + ch * 16, src + 64 + ch * 8);
        else
            cp16(sb + SK_BYTES + row * SKV_ROW + (ch - 8) * 16, src + 128 + (ch - 8) * 8);
    }
}

__device__ __forceinline__ void qk_mma(float s[8][4], const uint32_t qa[4][4],
                                       uint32_t skb, int lane) {
#pragma unroll
    for (int ni = 0; ni < 8; ni++)
#pragma unroll
        for (int r = 0; r < 4; r++) s[ni][r] = 0.f;
#pragma unroll
    for (int kd = 0; kd < 4; kd++) {
#pragma unroll
        for (int p = 0; p < 8; p += 2) {
            uint32_t b0, b1, b2, b3;
            uint32_t ad = skb + (8 * (p + (lane >> 4)) + (lane & 7)) * SKV_ROW
                              + 32 * kd + ((lane >> 3) & 1) * 16;
            ldsm4(b0, b1, b2, b3, ad);
            mma16(s[p],     qa[kd], b0, b1);
            mma16(s[p + 1], qa[kd], b2, b3);
        }
    }
}

__device__ __forceinline__ void pv_mma(float o[8][4], const uint32_t pp[4][4],
                                       uint32_t svb, int lane) {
#pragma unroll
    for (int kd = 0; kd < 4; kd++) {
#pragma unroll
        for (int p = 0; p < 8; p += 2) {
            uint32_t b0, b1, b2, b3;
            uint32_t ad = svb + (16 * kd + (lane & 15)) * SKV_ROW
                              + 16 * (p + (lane >> 4));
            ldsm4t(b0, b1, b2, b3, ad);
            mma16(o[p],     pp[kd], b0, b1);
            mma16(o[p + 1], pp[kd], b2, b3);
        }
    }
}

__device__ __forceinline__ void mask_diag(float s[8][4], int rowg, int k0c, int c) {
#pragma unroll
    for (int ni = 0; ni < 8; ni++) {
        int col = k0c + 8 * ni + 2 * c;
        if (col > rowg)         s[ni][0] = -1e30f;
        if (col + 1 > rowg)     s[ni][1] = -1e30f;
        if (col > rowg + 8)     s[ni][2] = -1e30f;
        if (col + 1 > rowg + 8) s[ni][3] = -1e30f;
    }
}

__device__ __forceinline__ void softmax_pack(float s[8][4], float o[8][4],
    float& m0r, float& m1r, float& l0r, float& l1r, uint32_t pp[4][4])
{
    float lm0 = -1e30f, lm1 = -1e30f;
#pragma unroll
    for (int ni = 0; ni < 8; ni++) {
        lm0 = fmaxf(lm0, fmaxf(s[ni][0], s[ni][1]));
        lm1 = fmaxf(lm1, fmaxf(s[ni][2], s[ni][3]));
    }
    lm0 = fmaxf(lm0, __shfl_xor_sync(0xffffffffu, lm0, 1));
    lm0 = fmaxf(lm0, __shfl_xor_sync(0xffffffffu, lm0, 2));
    lm1 = fmaxf(lm1, __shfl_xor_sync(0xffffffffu, lm1, 1));
    lm1 = fmaxf(lm1, __shfl_xor_sync(0xffffffffu, lm1, 2));
    float mn0 = fmaxf(m0r, lm0), mn1 = fmaxf(m1r, lm1);
    float al0 = ex2(m0r - mn0), al1 = ex2(m1r - mn1);
    m0r = mn0; m1r = mn1;
    float ls0 = 0.f, ls1 = 0.f;
#pragma unroll
    for (int ni = 0; ni < 8; ni++) {
        s[ni][0] = ex2(s[ni][0] - mn0); ls0 += s[ni][0];
        s[ni][1] = ex2(s[ni][1] - mn0); ls0 += s[ni][1];
        s[ni][2] = ex2(s[ni][2] - mn1); ls1 += s[ni][2];
        s[ni][3] = ex2(s[ni][3] - mn1); ls1 += s[ni][3];
    }
    ls0 += __shfl_xor_sync(0xffffffffu, ls0, 1);
    ls0 += __shfl_xor_sync(0xffffffffu, ls0, 2);
    ls1 += __shfl_xor_sync(0xffffffffu, ls1, 1);
    ls1 += __shfl_xor_sync(0xffffffffu, ls1, 2);
    l0r = l0r * al0 + ls0;
    l1r = l1r * al1 + ls1;
#pragma unroll
    for (int ni = 0; ni < 8; ni++) {
        o[ni][0] *= al0; o[ni][1] *= al0;
        o[ni][2] *= al1; o[ni][3] *= al1;
    }
#pragma unroll
    for (int kd = 0; kd < 4; kd++) {
        pp[kd][0] = packh2(s[2 * kd][0],     s[2 * kd][1]);
        pp[kd][1] = packh2(s[2 * kd][2],     s[2 * kd][3]);
        pp[kd][2] = packh2(s[2 * kd + 1][0], s[2 * kd + 1][1]);
        pp[kd][3] = packh2(s[2 * kd + 1][2], s[2 * kd + 1][3]);
    }
}

__global__ __launch_bounds__(128, 3) void attn_kernel(float* __restrict__ out)
{
    extern __shared__ char dsm[];
    const uint32_t smem_u32 = (uint32_t)__cvta_generic_to_shared(dsm);

    const int tid  = threadIdx.x;
    const int lane = tid & 31;
    const int w    = tid >> 5;
    const int g    = lane >> 2;
    const int c    = lane & 3;
    const int b    = blockIdx.y;
    const int qi   = (int)gridDim.x - 1 - (int)blockIdx.x;
    const int q0   = qi * 64;
    const size_t base = (size_t)b * SEQ * NQKV;
    const int rowg = q0 + 16 * w + g;

    issue_tile(smem_u32, g_qkv + base, tid);
    asm volatile("cp.async.commit_group;" ::: "memory");
    if (qi >= 1)
        issue_tile(smem_u32 + STAGE_B, g_qkv + base + (size_t)64 * NQKV, tid);
    asm volatile("cp.async.commit_group;" ::: "memory");

    uint32_t qa[4][4];
    {
        const __half* q0p = g_qkv + base + (size_t)(q0 + 16 * w + g) * NQKV;
        const __half* q1p = q0p + 8 * NQKV;
#pragma unroll
        for (int kd = 0; kd < 4; kd++) {
            qa[kd][0] = *(const uint32_t*)(q0p + 16 * kd + 2 * c);
            qa[kd][1] = *(const uint32_t*)(q1p + 16 * kd + 2 * c);
            qa[kd][2] = *(const uint32_t*)(q0p + 16 * kd + 2 * c + 8);
            qa[kd][3] = *(const uint32_t*)(q1p + 16 * kd + 2 * c + 8);
        }
    }

    float o[8][4];
#pragma unroll
    for (int ni = 0; ni < 8; ni++)
#pragma unroll
        for (int r = 0; r < 4; r++) o[ni][r] = 0.f;
    float m0r = -1e30f, m1r = -1e30f, l0r = 0.f, l1r = 0.f;

    float s[8][4];
    uint32_t pp[4][4];

    asm volatile("cp.async.wait_group 1;" ::: "memory");
    __syncthreads();
    qk_mma(s, qa, smem_u32, lane);
    if (qi == 0) mask_diag(s, rowg, 0, c);
    softmax_pack(s, o, m0r, m1r, l0r, l1r, pp);

    for (int jt = 0; jt < qi; jt++) {
        asm volatile("cp.async.wait_group 0;" ::: "memory");
        __syncthreads();
        if (jt + 2 <= qi)
            issue_tile(smem_u32 + ((jt + 2) % 3) * STAGE_B,
                       g_qkv + base + (size_t)((jt + 2) * 64) * NQKV, tid);
        asm volatile("cp.async.commit_group;" ::: "memory");

        const uint32_t sk1 = smem_u32 + ((jt + 1) % 3) * STAGE_B;
        const uint32_t sv0 = smem_u32 + (jt % 3) * STAGE_B + SK_BYTES;

        qk_mma(s, qa, sk1, lane);
        pv_mma(o, pp, sv0, lane);
        if (jt + 1 == qi) mask_diag(s, rowg, (jt + 1) * 64, c);
        softmax_pack(s, o, m0r, m1r, l0r, l1r, pp);
    }

    {
        const uint32_t sv = smem_u32 + (qi % 3) * STAGE_B + SK_BYTES;
        pv_mma(o, pp, sv, lane);
    }

    float inv0 = 1.f / l0r, inv1 = 1.f / l1r;
    size_t orow = (size_t)b * SEQ + q0 + 16 * w + g;
#pragma unroll
    for (int ni = 0; ni < 8; ni++) {
        int col = 8 * ni + 2 * c;
        *(float2*)&out[orow * HDIM + col] =
            make_float2(o[ni][0] * inv0, o[ni][1] * inv0);
        *(float2*)&out[(orow + 8) * HDIM + col] =
            make_float2(o[ni][2] * inv1, o[ni][3] * inv1);
    }
}

// ---------------------------------------------------------------------------
extern "C" void kernel_launch(void* const* d_in, const int* in_sizes, int n_in,
                              void* d_out, int out_size)
{
    const float* x  = (const float*)d_in[0];
    const float* Wq = (const float*)d_in[1];
    const float* bq = (const float*)d_in[2];
    const float* Wk = (const float*)d_in[3];
    const float* bk = (const float*)d_in[4];
    const float* Wv = (const float*)d_in[5];
    const float* bv = (const float*)d_in[6];
    float* out = (float*)d_out;

    wconv_kernel<<<(DMODEL * 96) / 256, 256>>>(Wq, Wk, Wv);

    cudaFuncSetAttribute(qkv_main, cudaFuncAttributeMaxDynamicSharedMemorySize, QKV_SMEM);
    qkv_main<<<(BATCH * SEQ) / 128, 512, QKV_SMEM>>>(x, bq, bk, bv);

    cudaFuncSetAttribute(attn_kernel, cudaFuncAttributeMaxDynamicSharedMemorySize, ATT_SMEM);
    dim3 grid(SEQ / 64, BATCH);
    attn_kernel<<<grid, 128, ATT_SMEM>>>(out);
}